// round 9
// baseline (speedup 1.0000x reference)
#include <cuda_runtime.h>
#include <mma.h>
#include <cstdint>

using namespace nvcuda;

#define FDIM 128
#define BPAD 132          // padded smem row stride (floats): kills 8-way bank conflicts
#define MAXN 200704
#define MAXE 602112
#define MAXB 256          // max scan blocks (256*1024 >= MAXN)
#define SBLK 512          // col_stats partial blocks

// Scratch (device globals; no allocation allowed)
__device__ float g_buf0[MAXN * FDIM];   // xw (GEMM output, pre-aggregation)
__device__ float g_buf1[MAXN * FDIM];   // layer-1 aggregated h1 (layer-2 GEMM input)
__device__ int   g_degi[MAXN];
__device__ float g_dinv[MAXN];
__device__ int   g_rowp[MAXN + 1];
__device__ int   g_cursor[MAXN];
__device__ int   g_bsum[MAXB];
__device__ int   g_boff[MAXB];
__device__ float2 g_edge[MAXE];         // packed (src-as-float-bits, coef)
__device__ float g_part_s[SBLK * FDIM]; // col_stats partial sums
__device__ float g_part_q[SBLK * FDIM]; // col_stats partial sumsq
__device__ float g_W1p[FDIM * FDIM];    // W1 / sigma  (standardization folded)
__device__ float g_c1[FDIM];            // -(mu/sigma) @ W1
__device__ int   g_ei64;                // edge_index is int64?
__device__ int   g_b64;                 // batch is int64?

// ---------------------------------------------------------------------------
__device__ __forceinline__ int load_idx(const void* p, long long e, int is64) {
    return is64 ? (int)((const long long*)p)[e] : ((const int*)p)[e];
}

// Detect int64 vs int32 by inspecting raw 32-bit words (values < 2^31 ->
// int64 little-endian has all odd words zero). Parallel probe.
__global__ void detect_dtype(const int* ei_w, int E, const int* b_w, int N) {
    __shared__ int nz;
    if (threadIdx.x == 0) nz = 0;
    __syncthreads();
    if (blockIdx.x == 0) {
        int lim = 2 * E < 2048 ? 2 * E : 2048;
        for (int i = 1 + 2 * threadIdx.x; i < lim; i += 2 * blockDim.x)
            if (ei_w[i] != 0) atomicAdd(&nz, 1);
        __syncthreads();
        if (threadIdx.x == 0) g_ei64 = (nz == 0) ? 1 : 0;
    } else {
        int start = N - 2048; if (start < 0) start = 0;
        for (int i = start + threadIdx.x; i < N; i += blockDim.x)
            if ((i & 1) && b_w[i] != 0) atomicAdd(&nz, 1);
        __syncthreads();
        if (threadIdx.x == 0) g_b64 = (nz == 0) ? 1 : 0;
    }
}

// Column partial sums / sums of squares of x; atomic-free (per-block slots).
__global__ void col_stats(const float* __restrict__ x, int N) {
    int col = threadIdx.x;  // blockDim = 128
    float s = 0.f, s2 = 0.f;
    for (int r = blockIdx.x; r < N; r += SBLK) {
        float v = x[(size_t)r * FDIM + col];
        s += v; s2 += v * v;
    }
    g_part_s[blockIdx.x * FDIM + col] = s;
    g_part_q[blockIdx.x * FDIM + col] = s2;
}

// Fold standardization into W1:  x_std @ W1 = x @ (W1/sigma) + c
__global__ void prep_kernel(const float* __restrict__ W1, int N) {
    __shared__ float mu[FDIM], isd[FDIM];
    int t = threadIdx.x;  // 128 threads
    float sum = 0.f, sq = 0.f;
    for (int b = 0; b < SBLK; b++) {
        sum += g_part_s[b * FDIM + t];
        sq  += g_part_q[b * FDIM + t];
    }
    float mean = sum / (float)N;
    float var = (sq - sum * mean) / (float)(N - 1);  // ddof=1
    mu[t] = mean;
    isd[t] = rsqrtf(var);
    __syncthreads();
    float c = 0.f;
    for (int f = 0; f < FDIM; f++) {
        float w = W1[f * FDIM + t];
        g_W1p[f * FDIM + t] = w * isd[f];
        c -= mu[f] * isd[f] * w;
    }
    g_c1[t] = c;
}

__global__ void zero_kernel(float* __restrict__ dout, int outN, int N) {
    int i = blockIdx.x * blockDim.x + threadIdx.x;
    if (i < N)    { g_degi[i] = 0; g_cursor[i] = 0; }
    if (i < outN) dout[i] = 0.f;
}

__global__ void deg_count(const void* __restrict__ ei, int E) {
    int e = blockIdx.x * blockDim.x + threadIdx.x;
    if (e < E) {
        int d = load_idx(ei, (long long)E + e, g_ei64);
        atomicAdd(&g_degi[d], 1);
    }
}

// ---------------------------------------------------------------------------
// CSR build: exclusive prefix sum of g_degi -> g_rowp, then bin edges.
__global__ void scan1(int N) {
    __shared__ int sh[256];
    int t = threadIdx.x;
    int base = blockIdx.x * 1024 + t * 4;
    int v[4]; int s = 0;
#pragma unroll
    for (int i = 0; i < 4; i++) {
        v[i] = (base + i < N) ? g_degi[base + i] : 0;
        s += v[i];
    }
    sh[t] = s; __syncthreads();
    for (int off = 1; off < 256; off <<= 1) {
        int x = (t >= off) ? sh[t - off] : 0;
        __syncthreads();
        sh[t] += x;
        __syncthreads();
    }
    int run = sh[t] - s;   // exclusive
    if (t == 255) g_bsum[blockIdx.x] = sh[255];
#pragma unroll
    for (int i = 0; i < 4; i++) {
        if (base + i < N) { g_rowp[base + i] = run; run += v[i]; }
    }
}

__global__ void scan2(int NB) {
    __shared__ int sh[256];
    int t = threadIdx.x;
    int v = (t < NB) ? g_bsum[t] : 0;
    sh[t] = v; __syncthreads();
    for (int off = 1; off < 256; off <<= 1) {
        int x = (t >= off) ? sh[t - off] : 0;
        __syncthreads();
        sh[t] += x;
        __syncthreads();
    }
    if (t < NB) g_boff[t] = sh[t] - v;
}

// scan3 + dinv fused (both elementwise over N).
__global__ void scan3(int N, int E) {
    int i = blockIdx.x * blockDim.x + threadIdx.x;
    if (i < N) {
        g_rowp[i] += g_boff[i >> 10];
        g_dinv[i] = rsqrtf((float)g_degi[i] + 1.0f);
    }
    if (i == 0) g_rowp[N] = E;
}

__global__ void bin_edges(const void* __restrict__ ei, int E) {
    int e = blockIdx.x * blockDim.x + threadIdx.x;
    if (e >= E) return;
    int is64 = g_ei64;
    int s = load_idx(ei, e, is64);
    int d = load_idx(ei, (long long)E + e, is64);
    int pos = g_rowp[d] + atomicAdd(&g_cursor[d], 1);
    g_edge[pos] = make_float2(__int_as_float(s), g_dinv[s] * g_dinv[d]);
}

// ---------------------------------------------------------------------------
// GEMM: C[M,128] = A[M,128] @ B[128,128]  (tf32 wmma, K=128 in padded smem).
// Writes only Cxw (+cvec). RELU_A: relu applied to A on load (layer 2).
template <bool RELU_A, bool ADD_C>
__global__ void gemm_kernel(const float* __restrict__ A, const float* __restrict__ B,
                            const float* __restrict__ cvec,
                            float* __restrict__ Cxw, int M)
{
    extern __shared__ float sB[];  // 128*BPAD floats (reused as epilogue stage)
    for (int i = threadIdx.x; i < FDIM * FDIM; i += blockDim.x) {
        int r = i >> 7, c = i & 127;
        sB[r * BPAD + c] = wmma::__float_to_tf32(B[i]);
    }
    __syncthreads();

    int warp = threadIdx.x >> 5;
    int lane = threadIdx.x & 31;
    int row0 = blockIdx.x * 128 + warp * 16;
    bool active = (row0 + 16) <= M;

    wmma::fragment<wmma::accumulator, 16, 16, 8, float> acc[8];
    if (active) {
#pragma unroll
        for (int n = 0; n < 8; n++) wmma::fill_fragment(acc[n], 0.f);
#pragma unroll
        for (int k = 0; k < FDIM; k += 8) {
            wmma::fragment<wmma::matrix_a, 16, 16, 8, wmma::precision::tf32, wmma::row_major> a;
            wmma::load_matrix_sync(a, A + (size_t)row0 * FDIM + k, FDIM);
#pragma unroll
            for (int t = 0; t < a.num_elements; t++) {
                float v = a.x[t];
                if (RELU_A) v = fmaxf(v, 0.f);
                a.x[t] = wmma::__float_to_tf32(v);
            }
#pragma unroll
            for (int n = 0; n < 8; n++) {
                wmma::fragment<wmma::matrix_b, 16, 16, 8, wmma::precision::tf32, wmma::row_major> b;
                wmma::load_matrix_sync(b, sB + k * BPAD + n * 16, BPAD);
                wmma::mma_sync(acc[n], a, b, acc[n]);
            }
        }
    }
    __syncthreads();
    if (active) {
        float* stage = sB + warp * 16 * BPAD;
#pragma unroll
        for (int n = 0; n < 8; n++)
            wmma::store_matrix_sync(stage + n * 16, acc[n], BPAD, wmma::mem_row_major);
        __syncwarp();
        for (int i = lane; i < 16 * FDIM; i += 32) {
            int r = i >> 7;
            int c = i & 127;
            float v = stage[r * BPAD + c];
            if (ADD_C) v += cvec[c];
            Cxw[(size_t)(row0 + r) * FDIM + c] = v;
        }
    }
}

// ---------------------------------------------------------------------------
__device__ __forceinline__ void red_add_v4(float* p, float4 v) {
    asm volatile("red.global.add.v4.f32 [%0], {%1, %2, %3, %4};"
                 :: "l"(p), "f"(v.x), "f"(v.y), "f"(v.z), "f"(v.w) : "memory");
}

// Atomic-free segmented aggregation: one warp owns one dst node's full row.
//   h[d] = sum_{e in seg(d)} coef[e]*xw[src[e]] + dinv[d]^2*xw[d] + bias
// POOL=false: write h to out[d] (layer 1).
// POOL=true:  out[batch[d]] += relu(h)  (layer 2 fused with global_add_pool).
template <bool POOL>
__global__ void aggregate(const float* __restrict__ xw, float* __restrict__ out,
                          const float* __restrict__ bias,
                          const void* __restrict__ batch, int N)
{
    int node = (int)((blockIdx.x * (unsigned)blockDim.x + threadIdx.x) >> 5);
    int lane = threadIdx.x & 31;
    if (node >= N) return;
    int beg = g_rowp[node];
    int end = g_rowp[node + 1];
    float4 acc = make_float4(0.f, 0.f, 0.f, 0.f);
    for (int e = beg; e < end; e++) {
        float2 ed = g_edge[e];
        int s = __float_as_int(ed.x);
        float c = ed.y;
        float4 v = __ldg((const float4*)(xw + (size_t)s * FDIM) + lane);
        acc.x += c * v.x; acc.y += c * v.y; acc.z += c * v.z; acc.w += c * v.w;
    }
    float di = g_dinv[node];
    float sc = di * di;
    float4 v = ((const float4*)(xw + (size_t)node * FDIM))[lane];
    float4 b = ((const float4*)bias)[lane];
    acc.x += sc * v.x + b.x;
    acc.y += sc * v.y + b.y;
    acc.z += sc * v.z + b.z;
    acc.w += sc * v.w + b.w;
    if (POOL) {
        acc.x = fmaxf(acc.x, 0.f); acc.y = fmaxf(acc.y, 0.f);
        acc.z = fmaxf(acc.z, 0.f); acc.w = fmaxf(acc.w, 0.f);
        int g = load_idx(batch, node, g_b64);
        red_add_v4(out + (size_t)g * FDIM + lane * 4, acc);
    } else {
        ((float4*)(out + (size_t)node * FDIM))[lane] = acc;
    }
}

// ---------------------------------------------------------------------------
extern "C" void kernel_launch(void* const* d_in, const int* in_sizes, int n_in,
                              void* d_out, int out_size)
{
    const float* x     = (const float*)d_in[0];
    const void*  ei    = d_in[1];          // [2,E], int32 or int64 (device-detected)
    const void*  batch = d_in[2];

    int N = in_sizes[0] / FDIM;
    int E = in_sizes[1] / 2;

    const float* wb[4] = {nullptr, nullptr, nullptr, nullptr};
    const int want[4] = {FDIM * FDIM, FDIM, FDIM * FDIM, FDIM};
    int slot = 0;
    for (int i = 3; i < n_in && slot < 4; i++) {
        if (in_sizes[i] <= 2) continue;
        if (in_sizes[i] == want[slot]) wb[slot++] = (const float*)d_in[i];
    }
    if (slot < 4 && n_in >= 7) {
        for (int k = 0; k < 4; k++) wb[k] = (const float*)d_in[n_in - 4 + k];
    }
    const float* W1 = wb[0];
    const float* b1 = wb[1];
    const float* W2 = wb[2];
    const float* b2 = wb[3];

    float* out = (float*)d_out;

    float *p0, *p1, *pW1p, *pc1;
    cudaGetSymbolAddress((void**)&p0,   g_buf0);
    cudaGetSymbolAddress((void**)&p1,   g_buf1);
    cudaGetSymbolAddress((void**)&pW1p, g_W1p);
    cudaGetSymbolAddress((void**)&pc1,  g_c1);

    const int SMEM = FDIM * BPAD * sizeof(float);  // 66 KB (padded)
    cudaFuncSetAttribute(gemm_kernel<false, true>,
                         cudaFuncAttributeMaxDynamicSharedMemorySize, SMEM);
    cudaFuncSetAttribute(gemm_kernel<true, false>,
                         cudaFuncAttributeMaxDynamicSharedMemorySize, SMEM);

    int gblocks = (N + 127) / 128;
    int ablocks = (N + 7) / 8;   // 8 warps (nodes) per 256-thread block
    int NB = (N + 1023) / 1024;

    // Launch order chosen so gemm1 sits in the ncu capture slot (4th launch).
    detect_dtype<<<2, 1024>>>((const int*)ei, E, (const int*)batch, N);       // 0
    col_stats<<<SBLK, 128>>>(x, N);                                           // 1
    prep_kernel<<<1, 128>>>(W1, N);                                           // 2
    gemm_kernel<false, true><<<gblocks, 256, SMEM>>>(x, pW1p, pc1, p0, N);    // 3 <- profiled
    zero_kernel<<<(N + 255) / 256, 256>>>(out, out_size, N);                  // 4
    deg_count<<<(E + 255) / 256, 256>>>(ei, E);                               // 5
    scan1<<<NB, 256>>>(N);                                                    // 6
    scan2<<<1, 256>>>(NB);                                                    // 7
    scan3<<<(N + 255) / 256, 256>>>(N, E);                                    // 8
    bin_edges<<<(E + 255) / 256, 256>>>(ei, E);                               // 9
    aggregate<false><<<ablocks, 256>>>(p0, p1, b1, batch, N);                 // 10
    gemm_kernel<true, false><<<gblocks, 256, SMEM>>>(p1, W2, nullptr, p0, N); // 11
    aggregate<true><<<ablocks, 256>>>(p0, out, b2, batch, N);                 // 12
}

// round 10
// speedup vs baseline: 1.0888x; 1.0888x over previous
#include <cuda_runtime.h>
#include <mma.h>
#include <cstdint>

using namespace nvcuda;

#define FDIM 128
#define BPAD 132          // padded smem row stride (floats): kills 8-way bank conflicts
#define MAXN 200704
#define MAXE 602112
#define MAXB 256          // max scan blocks (256*1024 >= MAXN)
#define SBLK 512          // col_stats partial blocks

// Scratch (device globals; no allocation allowed)
__device__ float g_buf0[MAXN * FDIM];   // xw (GEMM output, pre-aggregation)
__device__ float g_buf1[MAXN * FDIM];   // layer-1 aggregated h1 (layer-2 GEMM input)
__device__ int   g_degi[MAXN];
__device__ float g_dinv[MAXN];
__device__ int   g_rowp[MAXN + 1];
__device__ int   g_cursor[MAXN];
__device__ int   g_bsum[MAXB];
__device__ int   g_boff[MAXB];
__device__ float2 g_edge[MAXE];         // packed (src-as-float-bits, coef)
__device__ float g_part_s[SBLK * FDIM]; // col_stats partial sums
__device__ float g_part_q[SBLK * FDIM]; // col_stats partial sumsq
__device__ float g_W1p[FDIM * FDIM];    // W1 / sigma  (standardization folded)
__device__ float g_c1[FDIM];            // -(mu/sigma) @ W1
__device__ int   g_ei64;                // edge_index is int64?
__device__ int   g_b64;                 // batch is int64?

// ---------------------------------------------------------------------------
__device__ __forceinline__ int load_idx(const void* p, long long e, int is64) {
    return is64 ? (int)((const long long*)p)[e] : ((const int*)p)[e];
}

// Detect int64 vs int32 by inspecting raw 32-bit words (values < 2^31 ->
// int64 little-endian has all odd words zero). Parallel probe.
__global__ void detect_dtype(const int* ei_w, int E, const int* b_w, int N) {
    __shared__ int nz;
    if (threadIdx.x == 0) nz = 0;
    __syncthreads();
    if (blockIdx.x == 0) {
        int lim = 2 * E < 2048 ? 2 * E : 2048;
        for (int i = 1 + 2 * threadIdx.x; i < lim; i += 2 * blockDim.x)
            if (ei_w[i] != 0) atomicAdd(&nz, 1);
        __syncthreads();
        if (threadIdx.x == 0) g_ei64 = (nz == 0) ? 1 : 0;
    } else {
        int start = N - 2048; if (start < 0) start = 0;
        for (int i = start + threadIdx.x; i < N; i += blockDim.x)
            if ((i & 1) && b_w[i] != 0) atomicAdd(&nz, 1);
        __syncthreads();
        if (threadIdx.x == 0) g_b64 = (nz == 0) ? 1 : 0;
    }
}

// Column partial sums / sums of squares of x; atomic-free (per-block slots).
__global__ void col_stats(const float* __restrict__ x, int N) {
    int col = threadIdx.x;  // blockDim = 128
    float s = 0.f, s2 = 0.f;
    for (int r = blockIdx.x; r < N; r += SBLK) {
        float v = x[(size_t)r * FDIM + col];
        s += v; s2 += v * v;
    }
    g_part_s[blockIdx.x * FDIM + col] = s;
    g_part_q[blockIdx.x * FDIM + col] = s2;
}

// Fold standardization into W1:  x_std @ W1 = x @ (W1/sigma) + c
__global__ void prep_kernel(const float* __restrict__ W1, int N) {
    __shared__ float mu[FDIM], isd[FDIM];
    int t = threadIdx.x;  // 128 threads
    float sum = 0.f, sq = 0.f;
    for (int b = 0; b < SBLK; b++) {
        sum += g_part_s[b * FDIM + t];
        sq  += g_part_q[b * FDIM + t];
    }
    float mean = sum / (float)N;
    float var = (sq - sum * mean) / (float)(N - 1);  // ddof=1
    mu[t] = mean;
    isd[t] = rsqrtf(var);
    __syncthreads();
    float c = 0.f;
    for (int f = 0; f < FDIM; f++) {
        float w = W1[f * FDIM + t];
        g_W1p[f * FDIM + t] = w * isd[f];
        c -= mu[f] * isd[f] * w;
    }
    g_c1[t] = c;
}

__global__ void zero_kernel(float* __restrict__ dout, int outN, int N) {
    int i = blockIdx.x * blockDim.x + threadIdx.x;
    if (i < N)    { g_degi[i] = 0; g_cursor[i] = 0; }
    if (i < outN) dout[i] = 0.f;
}

__global__ void deg_count(const void* __restrict__ ei, int E) {
    int e = blockIdx.x * blockDim.x + threadIdx.x;
    if (e < E) {
        int d = load_idx(ei, (long long)E + e, g_ei64);
        atomicAdd(&g_degi[d], 1);
    }
}

// ---------------------------------------------------------------------------
// CSR build: exclusive prefix sum of g_degi -> g_rowp, then bin edges.
__global__ void scan1(int N) {
    __shared__ int sh[256];
    int t = threadIdx.x;
    int base = blockIdx.x * 1024 + t * 4;
    int v[4]; int s = 0;
#pragma unroll
    for (int i = 0; i < 4; i++) {
        v[i] = (base + i < N) ? g_degi[base + i] : 0;
        s += v[i];
    }
    sh[t] = s; __syncthreads();
    for (int off = 1; off < 256; off <<= 1) {
        int x = (t >= off) ? sh[t - off] : 0;
        __syncthreads();
        sh[t] += x;
        __syncthreads();
    }
    int run = sh[t] - s;   // exclusive
    if (t == 255) g_bsum[blockIdx.x] = sh[255];
#pragma unroll
    for (int i = 0; i < 4; i++) {
        if (base + i < N) { g_rowp[base + i] = run; run += v[i]; }
    }
}

__global__ void scan2(int NB) {
    __shared__ int sh[256];
    int t = threadIdx.x;
    int v = (t < NB) ? g_bsum[t] : 0;
    sh[t] = v; __syncthreads();
    for (int off = 1; off < 256; off <<= 1) {
        int x = (t >= off) ? sh[t - off] : 0;
        __syncthreads();
        sh[t] += x;
        __syncthreads();
    }
    if (t < NB) g_boff[t] = sh[t] - v;
}

// scan3 + dinv fused (both elementwise over N).
__global__ void scan3(int N, int E) {
    int i = blockIdx.x * blockDim.x + threadIdx.x;
    if (i < N) {
        g_rowp[i] += g_boff[i >> 10];
        g_dinv[i] = rsqrtf((float)g_degi[i] + 1.0f);
    }
    if (i == 0) g_rowp[N] = E;
}

__global__ void bin_edges(const void* __restrict__ ei, int E) {
    int e = blockIdx.x * blockDim.x + threadIdx.x;
    if (e >= E) return;
    int is64 = g_ei64;
    int s = load_idx(ei, e, is64);
    int d = load_idx(ei, (long long)E + e, is64);
    int pos = g_rowp[d] + atomicAdd(&g_cursor[d], 1);
    g_edge[pos] = make_float2(__int_as_float(s), g_dinv[s] * g_dinv[d]);
}

// ---------------------------------------------------------------------------
// GEMM: C[M,128] = A[M,128] @ B[128,128]  (tf32 wmma, B in padded smem).
// 512 threads = 16 warps x 16 rows = 256 rows per block; direct fragment
// stores to global (no smem staging; +c1 correction folded into aggregate).
// RELU_A: relu applied to A on load (layer 2).
template <bool RELU_A>
__global__ void __launch_bounds__(512)
gemm_kernel(const float* __restrict__ A, const float* __restrict__ B,
            float* __restrict__ Cxw, int M)
{
    extern __shared__ float sB[];  // 128*BPAD floats = 66 KB
    for (int i = threadIdx.x; i < FDIM * FDIM; i += blockDim.x) {
        int r = i >> 7, c = i & 127;
        sB[r * BPAD + c] = wmma::__float_to_tf32(B[i]);
    }
    __syncthreads();

    int warp = threadIdx.x >> 5;
    int row0 = blockIdx.x * 256 + warp * 16;
    if (row0 + 16 > M) return;

    wmma::fragment<wmma::accumulator, 16, 16, 8, float> acc[8];
#pragma unroll
    for (int n = 0; n < 8; n++) wmma::fill_fragment(acc[n], 0.f);
#pragma unroll
    for (int k = 0; k < FDIM; k += 8) {
        wmma::fragment<wmma::matrix_a, 16, 16, 8, wmma::precision::tf32, wmma::row_major> a;
        wmma::load_matrix_sync(a, A + (size_t)row0 * FDIM + k, FDIM);
#pragma unroll
        for (int t = 0; t < a.num_elements; t++) {
            float v = a.x[t];
            if (RELU_A) v = fmaxf(v, 0.f);
            a.x[t] = wmma::__float_to_tf32(v);
        }
#pragma unroll
        for (int n = 0; n < 8; n++) {
            wmma::fragment<wmma::matrix_b, 16, 16, 8, wmma::precision::tf32, wmma::row_major> b;
            wmma::load_matrix_sync(b, sB + k * BPAD + n * 16, BPAD);
            wmma::mma_sync(acc[n], a, b, acc[n]);
        }
    }
#pragma unroll
    for (int n = 0; n < 8; n++)
        wmma::store_matrix_sync(Cxw + (size_t)row0 * FDIM + n * 16, acc[n],
                                FDIM, wmma::mem_row_major);
}

// ---------------------------------------------------------------------------
__device__ __forceinline__ void red_add_v4(float* p, float4 v) {
    asm volatile("red.global.add.v4.f32 [%0], {%1, %2, %3, %4};"
                 :: "l"(p), "f"(v.x), "f"(v.y), "f"(v.z), "f"(v.w) : "memory");
}

// Atomic-free segmented aggregation: one warp owns one dst node's full row.
//   h[d] = sum_e coef_e*xw[src_e] + dinv_d^2*xw[d] (+ fac*c1) + bias
// where fac = sum_e coef_e + dinv_d^2 reconstructs the folded c1 column
// correction (ADD_C, layer 1 only).
// POOL=false: write h to out[d] (layer 1).
// POOL=true:  out[batch[d]] += relu(h)  (layer 2 fused with global_add_pool).
template <bool POOL, bool ADD_C>
__global__ void aggregate(const float* __restrict__ xw, float* __restrict__ out,
                          const float* __restrict__ bias, const float* __restrict__ cvec,
                          const void* __restrict__ batch, int N)
{
    int node = (int)((blockIdx.x * (unsigned)blockDim.x + threadIdx.x) >> 5);
    int lane = threadIdx.x & 31;
    if (node >= N) return;
    int beg = g_rowp[node];
    int end = g_rowp[node + 1];
    float4 acc = make_float4(0.f, 0.f, 0.f, 0.f);
    float csum = 0.f;
    for (int e = beg; e < end; e++) {
        float2 ed = g_edge[e];
        int s = __float_as_int(ed.x);
        float c = ed.y;
        csum += c;
        float4 v = __ldg((const float4*)(xw + (size_t)s * FDIM) + lane);
        acc.x += c * v.x; acc.y += c * v.y; acc.z += c * v.z; acc.w += c * v.w;
    }
    float di = g_dinv[node];
    float sc = di * di;
    float fac = csum + sc;
    float4 v = ((const float4*)(xw + (size_t)node * FDIM))[lane];
    float4 b = ((const float4*)bias)[lane];
    acc.x += sc * v.x + b.x;
    acc.y += sc * v.y + b.y;
    acc.z += sc * v.z + b.z;
    acc.w += sc * v.w + b.w;
    if (ADD_C) {
        float4 cv = ((const float4*)cvec)[lane];
        acc.x += fac * cv.x; acc.y += fac * cv.y;
        acc.z += fac * cv.z; acc.w += fac * cv.w;
    }
    if (POOL) {
        acc.x = fmaxf(acc.x, 0.f); acc.y = fmaxf(acc.y, 0.f);
        acc.z = fmaxf(acc.z, 0.f); acc.w = fmaxf(acc.w, 0.f);
        int g = load_idx(batch, node, g_b64);
        red_add_v4(out + (size_t)g * FDIM + lane * 4, acc);
    } else {
        ((float4*)(out + (size_t)node * FDIM))[lane] = acc;
    }
}

// ---------------------------------------------------------------------------
extern "C" void kernel_launch(void* const* d_in, const int* in_sizes, int n_in,
                              void* d_out, int out_size)
{
    const float* x     = (const float*)d_in[0];
    const void*  ei    = d_in[1];          // [2,E], int32 or int64 (device-detected)
    const void*  batch = d_in[2];

    int N = in_sizes[0] / FDIM;
    int E = in_sizes[1] / 2;

    const float* wb[4] = {nullptr, nullptr, nullptr, nullptr};
    const int want[4] = {FDIM * FDIM, FDIM, FDIM * FDIM, FDIM};
    int slot = 0;
    for (int i = 3; i < n_in && slot < 4; i++) {
        if (in_sizes[i] <= 2) continue;
        if (in_sizes[i] == want[slot]) wb[slot++] = (const float*)d_in[i];
    }
    if (slot < 4 && n_in >= 7) {
        for (int k = 0; k < 4; k++) wb[k] = (const float*)d_in[n_in - 4 + k];
    }
    const float* W1 = wb[0];
    const float* b1 = wb[1];
    const float* W2 = wb[2];
    const float* b2 = wb[3];

    float* out = (float*)d_out;

    float *p0, *p1, *pW1p, *pc1;
    cudaGetSymbolAddress((void**)&p0,   g_buf0);
    cudaGetSymbolAddress((void**)&p1,   g_buf1);
    cudaGetSymbolAddress((void**)&pW1p, g_W1p);
    cudaGetSymbolAddress((void**)&pc1,  g_c1);

    const int SMEM = FDIM * BPAD * sizeof(float);  // 66 KB (padded)
    cudaFuncSetAttribute(gemm_kernel<false>,
                         cudaFuncAttributeMaxDynamicSharedMemorySize, SMEM);
    cudaFuncSetAttribute(gemm_kernel<true>,
                         cudaFuncAttributeMaxDynamicSharedMemorySize, SMEM);

    int gblocks = (N + 255) / 256;
    int ablocks = (N + 7) / 8;   // 8 warps (nodes) per 256-thread block
    int NB = (N + 1023) / 1024;

    // Launch order chosen so gemm1 sits in the ncu capture slot (4th launch).
    detect_dtype<<<2, 1024>>>((const int*)ei, E, (const int*)batch, N);       // 0
    col_stats<<<SBLK, 128>>>(x, N);                                           // 1
    prep_kernel<<<1, 128>>>(W1, N);                                           // 2
    gemm_kernel<false><<<gblocks, 512, SMEM>>>(x, pW1p, p0, N);               // 3 <- profiled
    zero_kernel<<<(N + 255) / 256, 256>>>(out, out_size, N);                  // 4
    deg_count<<<(E + 255) / 256, 256>>>(ei, E);                               // 5
    scan1<<<NB, 256>>>(N);                                                    // 6
    scan2<<<1, 256>>>(NB);                                                    // 7
    scan3<<<(N + 255) / 256, 256>>>(N, E);                                    // 8
    bin_edges<<<(E + 255) / 256, 256>>>(ei, E);                               // 9
    aggregate<false, true><<<ablocks, 256>>>(p0, p1, b1, pc1, batch, N);      // 10
    gemm_kernel<true><<<gblocks, 512, SMEM>>>(p1, W2, p0, N);                 // 11
    aggregate<true, false><<<ablocks, 256>>>(p0, out, b2, nullptr, batch, N); // 12
}

// round 13
// speedup vs baseline: 1.1182x; 1.0269x over previous
#include <cuda_runtime.h>
#include <mma.h>
#include <cstdint>

using namespace nvcuda;

#define FDIM 128
#define BPAD 132          // padded smem row stride (floats): kills 8-way bank conflicts
#define MAXN 200704
#define MAXE 602112
#define MAXB 256          // max scan blocks (256*1024 >= MAXN)
#define SBLK 512          // col_stats partial blocks

// Scratch (device globals; no allocation allowed)
__device__ float g_buf0[MAXN * FDIM];   // xw (GEMM output, pre-aggregation)
__device__ float g_buf1[MAXN * FDIM];   // layer-1 aggregated h1 (layer-2 GEMM input)
__device__ int   g_degi[MAXN];
__device__ float g_dinv[MAXN];
__device__ int   g_rowp[MAXN + 1];
__device__ int   g_cursor[MAXN];
__device__ int   g_bsum[MAXB];
__device__ int   g_boff[MAXB];
__device__ float2 g_edge[MAXE];         // packed (src-as-float-bits, coef)
__device__ float g_part_s[SBLK * FDIM]; // col_stats partial sums
__device__ float g_part_q[SBLK * FDIM]; // col_stats partial sumsq
__device__ float g_W1p[FDIM * FDIM];    // W1 / sigma  (standardization folded)
__device__ float g_c1[FDIM];            // -(mu/sigma) @ W1
__device__ int   g_ei64;                // edge_index is int64?
__device__ int   g_b64;                 // batch is int64?

// ---------------------------------------------------------------------------
__device__ __forceinline__ int load_idx(const void* p, long long e, int is64) {
    return is64 ? (int)((const long long*)p)[e] : ((const int*)p)[e];
}

// Detect int64 vs int32 by inspecting raw 32-bit words (values < 2^31 ->
// int64 little-endian has all odd words zero). Parallel probe.
__global__ void detect_dtype(const int* ei_w, int E, const int* b_w, int N) {
    __shared__ int nz;
    if (threadIdx.x == 0) nz = 0;
    __syncthreads();
    if (blockIdx.x == 0) {
        int lim = 2 * E < 2048 ? 2 * E : 2048;
        for (int i = 1 + 2 * threadIdx.x; i < lim; i += 2 * blockDim.x)
            if (ei_w[i] != 0) atomicAdd(&nz, 1);
        __syncthreads();
        if (threadIdx.x == 0) g_ei64 = (nz == 0) ? 1 : 0;
    } else {
        int start = N - 2048; if (start < 0) start = 0;
        for (int i = start + threadIdx.x; i < N; i += blockDim.x)
            if ((i & 1) && b_w[i] != 0) atomicAdd(&nz, 1);
        __syncthreads();
        if (threadIdx.x == 0) g_b64 = (nz == 0) ? 1 : 0;
    }
}

// Column partial sums / sums of squares of x; atomic-free (per-block slots).
__global__ void col_stats(const float* __restrict__ x, int N) {
    int col = threadIdx.x;  // blockDim = 128
    float s = 0.f, s2 = 0.f;
    for (int r = blockIdx.x; r < N; r += SBLK) {
        float v = x[(size_t)r * FDIM + col];
        s += v; s2 += v * v;
    }
    g_part_s[blockIdx.x * FDIM + col] = s;
    g_part_q[blockIdx.x * FDIM + col] = s2;
}

// Fold standardization into W1:  x_std @ W1 = x @ (W1/sigma) + c
__global__ void prep_kernel(const float* __restrict__ W1, int N) {
    __shared__ float mu[FDIM], isd[FDIM];
    int t = threadIdx.x;  // 128 threads
    float sum = 0.f, sq = 0.f;
    for (int b = 0; b < SBLK; b++) {
        sum += g_part_s[b * FDIM + t];
        sq  += g_part_q[b * FDIM + t];
    }
    float mean = sum / (float)N;
    float var = (sq - sum * mean) / (float)(N - 1);  // ddof=1
    mu[t] = mean;
    isd[t] = rsqrtf(var);
    __syncthreads();
    float c = 0.f;
    for (int f = 0; f < FDIM; f++) {
        float w = W1[f * FDIM + t];
        g_W1p[f * FDIM + t] = w * isd[f];
        c -= mu[f] * isd[f] * w;
    }
    g_c1[t] = c;
}

__global__ void zero_kernel(float* __restrict__ dout, int outN, int N) {
    int i = blockIdx.x * blockDim.x + threadIdx.x;
    if (i < N)    { g_degi[i] = 0; g_cursor[i] = 0; }
    if (i < outN) dout[i] = 0.f;
}

__global__ void deg_count(const void* __restrict__ ei, int E) {
    int e = blockIdx.x * blockDim.x + threadIdx.x;
    if (e < E) {
        int d = load_idx(ei, (long long)E + e, g_ei64);
        atomicAdd(&g_degi[d], 1);
    }
}

// ---------------------------------------------------------------------------
// CSR build: exclusive prefix sum of g_degi -> g_rowp, then bin edges.
__global__ void scan1(int N) {
    __shared__ int sh[256];
    int t = threadIdx.x;
    int base = blockIdx.x * 1024 + t * 4;
    int v[4]; int s = 0;
#pragma unroll
    for (int i = 0; i < 4; i++) {
        v[i] = (base + i < N) ? g_degi[base + i] : 0;
        s += v[i];
    }
    sh[t] = s; __syncthreads();
    for (int off = 1; off < 256; off <<= 1) {
        int x = (t >= off) ? sh[t - off] : 0;
        __syncthreads();
        sh[t] += x;
        __syncthreads();
    }
    int run = sh[t] - s;   // exclusive
    if (t == 255) g_bsum[blockIdx.x] = sh[255];
#pragma unroll
    for (int i = 0; i < 4; i++) {
        if (base + i < N) { g_rowp[base + i] = run; run += v[i]; }
    }
}

__global__ void scan2(int NB) {
    __shared__ int sh[256];
    int t = threadIdx.x;
    int v = (t < NB) ? g_bsum[t] : 0;
    sh[t] = v; __syncthreads();
    for (int off = 1; off < 256; off <<= 1) {
        int x = (t >= off) ? sh[t - off] : 0;
        __syncthreads();
        sh[t] += x;
        __syncthreads();
    }
    if (t < NB) g_boff[t] = sh[t] - v;
}

// scan3 + dinv fused (both elementwise over N).
__global__ void scan3(int N, int E) {
    int i = blockIdx.x * blockDim.x + threadIdx.x;
    if (i < N) {
        g_rowp[i] += g_boff[i >> 10];
        g_dinv[i] = rsqrtf((float)g_degi[i] + 1.0f);
    }
    if (i == 0) g_rowp[N] = E;
}

__global__ void bin_edges(const void* __restrict__ ei, int E) {
    int e = blockIdx.x * blockDim.x + threadIdx.x;
    if (e >= E) return;
    int is64 = g_ei64;
    int s = load_idx(ei, e, is64);
    int d = load_idx(ei, (long long)E + e, is64);
    int pos = g_rowp[d] + atomicAdd(&g_cursor[d], 1);
    g_edge[pos] = make_float2(__int_as_float(s), g_dinv[s] * g_dinv[d]);
}

// ---------------------------------------------------------------------------
// GEMM: C[M,128] = A[M,128] @ B[128,128]  (tf32 wmma, B in padded smem).
// 256 threads = 8 warps; warp tile 32x64 (2x4 m16n16k8 fragments), block tile
// 128x128 (warps arranged 4 m-tiles x 2 n-tiles). Halves smem B-fragment
// traffic per FLOP vs 16x128 warp strips. 2 blocks/SM (launch_bounds).
// RELU_A: relu applied to A on load (layer 2).
template <bool RELU_A>
__global__ void __launch_bounds__(256, 2)
gemm_kernel(const float* __restrict__ A, const float* __restrict__ B,
            float* __restrict__ Cxw, int M)
{
    extern __shared__ float sB[];  // 128*BPAD floats = 66 KB
    for (int i = threadIdx.x; i < FDIM * FDIM; i += blockDim.x) {
        int r = i >> 7, c = i & 127;
        sB[r * BPAD + c] = wmma::__float_to_tf32(B[i]);
    }
    __syncthreads();

    int warp = threadIdx.x >> 5;
    int mrow = warp & 3;        // 0..3  -> M offset
    int ncol = warp >> 2;       // 0..1  -> N offset
    int row0 = blockIdx.x * 128 + mrow * 32;
    int col0 = ncol * 64;
    if (row0 + 32 > M) return;

    wmma::fragment<wmma::accumulator, 16, 16, 8, float> acc[2][4];
#pragma unroll
    for (int i = 0; i < 2; i++)
#pragma unroll
        for (int j = 0; j < 4; j++) wmma::fill_fragment(acc[i][j], 0.f);

#pragma unroll
    for (int k = 0; k < FDIM; k += 8) {
        wmma::fragment<wmma::matrix_a, 16, 16, 8, wmma::precision::tf32, wmma::row_major> a[2];
#pragma unroll
        for (int i = 0; i < 2; i++) {
            wmma::load_matrix_sync(a[i], A + (size_t)(row0 + i * 16) * FDIM + k, FDIM);
#pragma unroll
            for (int t = 0; t < a[i].num_elements; t++) {
                float v = a[i].x[t];
                if (RELU_A) v = fmaxf(v, 0.f);
                a[i].x[t] = wmma::__float_to_tf32(v);
            }
        }
        wmma::fragment<wmma::matrix_b, 16, 16, 8, wmma::precision::tf32, wmma::row_major> b[4];
#pragma unroll
        for (int j = 0; j < 4; j++)
            wmma::load_matrix_sync(b[j], sB + k * BPAD + col0 + j * 16, BPAD);
#pragma unroll
        for (int i = 0; i < 2; i++)
#pragma unroll
            for (int j = 0; j < 4; j++)
                wmma::mma_sync(acc[i][j], a[i], b[j], acc[i][j]);
    }

#pragma unroll
    for (int i = 0; i < 2; i++)
#pragma unroll
        for (int j = 0; j < 4; j++)
            wmma::store_matrix_sync(Cxw + (size_t)(row0 + i * 16) * FDIM + col0 + j * 16,
                                    acc[i][j], FDIM, wmma::mem_row_major);
}

// ---------------------------------------------------------------------------
__device__ __forceinline__ void red_add_v4(float* p, float4 v) {
    asm volatile("red.global.add.v4.f32 [%0], {%1, %2, %3, %4};"
                 :: "l"(p), "f"(v.x), "f"(v.y), "f"(v.z), "f"(v.w) : "memory");
}

// Atomic-free segmented aggregation: one warp owns one dst node's full row.
//   h[d] = sum_e coef_e*xw[src_e] + dinv_d^2*xw[d] (+ fac*c1) + bias
// fac = sum_e coef_e + dinv_d^2 reconstructs the folded c1 column correction.
// POOL=false: write h to out[d] (layer 1).
// POOL=true:  out[batch[d]] += relu(h)  (layer 2 fused with global_add_pool).
template <bool POOL, bool ADD_C>
__global__ void aggregate(const float* __restrict__ xw, float* __restrict__ out,
                          const float* __restrict__ bias, const float* __restrict__ cvec,
                          const void* __restrict__ batch, int N)
{
    int node = (int)((blockIdx.x * (unsigned)blockDim.x + threadIdx.x) >> 5);
    int lane = threadIdx.x & 31;
    if (node >= N) return;
    int beg = g_rowp[node];
    int end = g_rowp[node + 1];
    float4 acc = make_float4(0.f, 0.f, 0.f, 0.f);
    float csum = 0.f;
    for (int e = beg; e < end; e++) {
        float2 ed = g_edge[e];
        int s = __float_as_int(ed.x);
        float c = ed.y;
        csum += c;
        float4 v = __ldg((const float4*)(xw + (size_t)s * FDIM) + lane);
        acc.x += c * v.x; acc.y += c * v.y; acc.z += c * v.z; acc.w += c * v.w;
    }
    float di = g_dinv[node];
    float sc = di * di;
    float fac = csum + sc;
    float4 v = ((const float4*)(xw + (size_t)node * FDIM))[lane];
    float4 b = ((const float4*)bias)[lane];
    acc.x += sc * v.x + b.x;
    acc.y += sc * v.y + b.y;
    acc.z += sc * v.z + b.z;
    acc.w += sc * v.w + b.w;
    if (ADD_C) {
        float4 cv = ((const float4*)cvec)[lane];
        acc.x += fac * cv.x; acc.y += fac * cv.y;
        acc.z += fac * cv.z; acc.w += fac * cv.w;
    }
    if (POOL) {
        acc.x = fmaxf(acc.x, 0.f); acc.y = fmaxf(acc.y, 0.f);
        acc.z = fmaxf(acc.z, 0.f); acc.w = fmaxf(acc.w, 0.f);
        int g = load_idx(batch, node, g_b64);
        red_add_v4(out + (size_t)g * FDIM + lane * 4, acc);
    } else {
        ((float4*)(out + (size_t)node * FDIM))[lane] = acc;
    }
}

// ---------------------------------------------------------------------------
extern "C" void kernel_launch(void* const* d_in, const int* in_sizes, int n_in,
                              void* d_out, int out_size)
{
    const float* x     = (const float*)d_in[0];
    const void*  ei    = d_in[1];          // [2,E], int32 or int64 (device-detected)
    const void*  batch = d_in[2];

    int N = in_sizes[0] / FDIM;
    int E = in_sizes[1] / 2;

    const float* wb[4] = {nullptr, nullptr, nullptr, nullptr};
    const int want[4] = {FDIM * FDIM, FDIM, FDIM * FDIM, FDIM};
    int slot = 0;
    for (int i = 3; i < n_in && slot < 4; i++) {
        if (in_sizes[i] <= 2) continue;
        if (in_sizes[i] == want[slot]) wb[slot++] = (const float*)d_in[i];
    }
    if (slot < 4 && n_in >= 7) {
        for (int k = 0; k < 4; k++) wb[k] = (const float*)d_in[n_in - 4 + k];
    }
    const float* W1 = wb[0];
    const float* b1 = wb[1];
    const float* W2 = wb[2];
    const float* b2 = wb[3];

    float* out = (float*)d_out;

    float *p0, *p1, *pW1p, *pc1;
    cudaGetSymbolAddress((void**)&p0,   g_buf0);
    cudaGetSymbolAddress((void**)&p1,   g_buf1);
    cudaGetSymbolAddress((void**)&pW1p, g_W1p);
    cudaGetSymbolAddress((void**)&pc1,  g_c1);

    const int SMEM = FDIM * BPAD * sizeof(float);  // 66 KB (padded)
    cudaFuncSetAttribute(gemm_kernel<false>,
                         cudaFuncAttributeMaxDynamicSharedMemorySize, SMEM);
    cudaFuncSetAttribute(gemm_kernel<true>,
                         cudaFuncAttributeMaxDynamicSharedMemorySize, SMEM);

    int gblocks = (N + 127) / 128;
    int ablocks = (N + 7) / 8;   // 8 warps (nodes) per 256-thread block
    int NB = (N + 1023) / 1024;

    // Launch order chosen so gemm1 sits in the ncu capture slot (4th launch).
    detect_dtype<<<2, 1024>>>((const int*)ei, E, (const int*)batch, N);       // 0
    col_stats<<<SBLK, 128>>>(x, N);                                           // 1
    prep_kernel<<<1, 128>>>(W1, N);                                           // 2
    gemm_kernel<false><<<gblocks, 256, SMEM>>>(x, pW1p, p0, N);               // 3 <- profiled
    zero_kernel<<<(N + 255) / 256, 256>>>(out, out_size, N);                  // 4
    deg_count<<<(E + 255) / 256, 256>>>(ei, E);                               // 5
    scan1<<<NB, 256>>>(N);                                                    // 6
    scan2<<<1, 256>>>(NB);                                                    // 7
    scan3<<<(N + 255) / 256, 256>>>(N, E);                                    // 8
    bin_edges<<<(E + 255) / 256, 256>>>(ei, E);                               // 9
    aggregate<false, true><<<ablocks, 256>>>(p0, p1, b1, pc1, batch, N);      // 10
    gemm_kernel<true><<<gblocks, 256, SMEM>>>(p1, W2, p0, N);                 // 11
    aggregate<true, false><<<ablocks, 256>>>(p0, out, b2, nullptr, batch, N); // 12
}